// round 9
// baseline (speedup 1.0000x reference)
#include <cuda_runtime.h>
#include <math.h>

// SimilarityTreeLSTM on GB300: level-parallel tree evaluation in one
// persistent kernel with a software grid barrier.
//
// R8 changes vs R7 (1923us):
//  * hW_leaf[v] = h_leaf[v] @ Wiouh per-vocab table; leaf scatter folds leaf
//    children directly into a 768-wide per-node iou accumulator (g_iouacc).
//  * g_hsum now holds only INTERNAL-children h. Internal nodes with no
//    internal children ("pre-leaves", ~half) skip the Wiouh matvec (196K of
//    262K MACs). Per-level order is split matvec-first / lite-second.
//  * FMA floor ~0.98ms -> ~0.67ms.

#define NNODE 65536
#define TOT   (2 * NNODE)
#define M     256
#define M3    (3 * M)
#define VOCAB 1000
#define VNB   8
#define MAXD_CAP 65536

// ---------------- device scratch (static: no allocations allowed) ----------
__device__ float g_hsum[TOT * M];        // 134 MB: internal-children h sum
__device__ float g_fcsum[TOT * M];       // 134 MB
__device__ float g_iouacc[TOT * M3];     // 402 MB: leaf-children iou contrib
__device__ float g_ioux[VOCAB * M3];     // vocab proj: emb@Wioux + bioux
__device__ float g_fxp[VOCAB * M];       // vocab proj: emb@Wfx + bfx
__device__ float g_hleaf[VOCAB * M];     // leaf h by token
__device__ float g_cleaf[VOCAB * M];     // leaf c by token
__device__ float g_hfw[VOCAB * M];       // h_leaf @ Wfh + bfh
__device__ float g_hwl[VOCAB * M3];      // h_leaf @ Wiouh
__device__ int   g_nchild[TOT];
__device__ int   g_nichild[TOT];         // # internal children
__device__ int   g_depth[TOT];
__device__ int   g_order[TOT];           // internal nodes by level (matvec|lite)
__device__ int   g_leaf[TOT];            // leaf nodes
__device__ int   g_nleaf;
__device__ int   g_hist1[MAXD_CAP];      // internal w/ internal children
__device__ int   g_hist0[MAXD_CAP];      // internal w/o internal children
__device__ int   g_startv[MAXD_CAP];
__device__ int   g_cur1[MAXD_CAP];
__device__ int   g_cur0[MAXD_CAP];
__device__ int   g_maxd;
__device__ float g_croot[2 * M];
__device__ unsigned g_barcnt;
__device__ unsigned g_sense;

__device__ __forceinline__ float sigf(float x) {
    return 1.0f / (1.0f + expf(-x));
}

// Sense-reversal grid barrier. Requires all blocks co-resident.
__device__ __forceinline__ void gsync() {
    __syncthreads();
    if (threadIdx.x == 0) {
        __threadfence();
        unsigned target = *((volatile unsigned*)&g_sense) + 1u;
        unsigned a = atomicAdd(&g_barcnt, 1u);
        if (a == gridDim.x - 1u) {
            g_barcnt = 0u;
            __threadfence();
            atomicExch(&g_sense, target);
        } else {
            while (*((volatile unsigned*)&g_sense) != target) { __nanosleep(64); }
        }
        __threadfence();
    }
    __syncthreads();
}

// Process a sub-range of one internal-node level, NT nodes per block-group.
// MATVEC=false: nodes have no internal children -> h_sum==0, skip Wiouh.
template <int NT, bool MATVEC>
__device__ void do_level(int s0, int cnt,
                         const int* __restrict__ l_tok, const int* __restrict__ l_par,
                         const int* __restrict__ r_tok, const int* __restrict__ r_par,
                         const float* __restrict__ Wiouh, const float* __restrict__ Wfh,
                         float bio0, float bio1, float bio2, float bfh_t,
                         float* s_f, int* s_node, int* s_tok, int* s_parg, int* s_ptok)
{
    const int t = threadIdx.x;
    const int ngrp = (cnt + NT - 1) / NT;

    for (int g = blockIdx.x; g < ngrp; g += gridDim.x) {
        const int base = s0 + g * NT;
        const int nn   = min(NT, cnt - g * NT);
        if (t < NT) {
            int idx  = base + ((t < nn) ? t : 0);    // clamp (dup node 0 of grp)
            int node = g_order[idx];
            int tree = node >> 16, loc = node & (NNODE - 1);
            const int* tokp = tree ? r_tok : l_tok;
            const int* parp = tree ? r_par : l_par;
            int pl = parp[loc];
            s_node[t] = node;
            s_tok[t]  = tokp[loc];
            s_parg[t] = (tree << 16) + pl;
            s_ptok[t] = tokp[pl];
        }
        __syncthreads();

        if (MATVEC) {
            // load internal-children h sums (bypass L1: updated via L2 atomics)
            #pragma unroll
            for (int n = 0; n < NT; n++)
                s_f[n * M + t] = __ldcg(&g_hsum[s_node[n] * M + t]);
            __syncthreads();
        }

        float a0[NT], a1[NT], a2[NT];
        #pragma unroll
        for (int n = 0; n < NT; n++) {
            int tk = s_tok[n];
            long nb = (long)s_node[n] * M3;
            a0[n] = g_ioux[tk * M3 + t]         + bio0 + __ldcg(&g_iouacc[nb + t]);
            a1[n] = g_ioux[tk * M3 + M + t]     + bio1 + __ldcg(&g_iouacc[nb + M + t]);
            a2[n] = g_ioux[tk * M3 + 2 * M + t] + bio2 + __ldcg(&g_iouacc[nb + 2 * M + t]);
        }

        if (MATVEC) {
            // ---- Wiouh matvec: explicit two-phase weight double-buffer ----
            float wa0[4], wa1[4], wa2[4], wb0[4], wb1[4], wb2[4];
            #pragma unroll
            for (int kk = 0; kk < 4; kk++) {
                wa0[kk] = Wiouh[kk * M3 + t];
                wa1[kk] = Wiouh[kk * M3 + M + t];
                wa2[kk] = Wiouh[kk * M3 + 2 * M + t];
            }
            #pragma unroll 1
            for (int k = 0; k < M; k += 8) {
                #pragma unroll
                for (int kk = 0; kk < 4; kk++) {
                    wb0[kk] = Wiouh[(k + 4 + kk) * M3 + t];
                    wb1[kk] = Wiouh[(k + 4 + kk) * M3 + M + t];
                    wb2[kk] = Wiouh[(k + 4 + kk) * M3 + 2 * M + t];
                }
                #pragma unroll
                for (int n = 0; n < NT; n++) {
                    const float4 h4 = *reinterpret_cast<const float4*>(s_f + n * M + k);
                    a0[n] += h4.x * wa0[0]; a1[n] += h4.x * wa1[0]; a2[n] += h4.x * wa2[0];
                    a0[n] += h4.y * wa0[1]; a1[n] += h4.y * wa1[1]; a2[n] += h4.y * wa2[1];
                    a0[n] += h4.z * wa0[2]; a1[n] += h4.z * wa1[2]; a2[n] += h4.z * wa2[2];
                    a0[n] += h4.w * wa0[3]; a1[n] += h4.w * wa1[3]; a2[n] += h4.w * wa2[3];
                }
                if (k + 8 < M) {
                    #pragma unroll
                    for (int kk = 0; kk < 4; kk++) {
                        wa0[kk] = Wiouh[(k + 8 + kk) * M3 + t];
                        wa1[kk] = Wiouh[(k + 8 + kk) * M3 + M + t];
                        wa2[kk] = Wiouh[(k + 8 + kk) * M3 + 2 * M + t];
                    }
                }
                #pragma unroll
                for (int n = 0; n < NT; n++) {
                    const float4 h4 = *reinterpret_cast<const float4*>(s_f + n * M + k + 4);
                    a0[n] += h4.x * wb0[0]; a1[n] += h4.x * wb1[0]; a2[n] += h4.x * wb2[0];
                    a0[n] += h4.y * wb0[1]; a1[n] += h4.y * wb1[1]; a2[n] += h4.y * wb2[1];
                    a0[n] += h4.z * wb0[2]; a1[n] += h4.z * wb1[2]; a2[n] += h4.z * wb2[2];
                    a0[n] += h4.w * wb0[3]; a1[n] += h4.w * wb1[3]; a2[n] += h4.w * wb2[3];
                }
            }
        }

        float cv[NT], hv[NT];
        #pragma unroll
        for (int n = 0; n < NT; n++) {
            float fc = __ldcg(&g_fcsum[s_node[n] * M + t]);
            float ig = sigf(a0[n]);
            float og = sigf(a1[n]);
            float ug = tanhf(a2[n]);
            cv[n] = ig * ug + fc;
            hv[n] = og * tanhf(cv[n]);
        }
        __syncthreads();                 // s_f reuse boundary
        #pragma unroll
        for (int n = 0; n < NT; n++) s_f[n * M + t] = hv[n];
        __syncthreads();

        float b[NT];
        #pragma unroll
        for (int n = 0; n < NT; n++)
            b[n] = bfh_t + g_fxp[s_ptok[n] * M + t];

        // ---- Wfh matvec: explicit two-phase weight double-buffer ----
        {
            float wa[4], wb[4];
            #pragma unroll
            for (int kk = 0; kk < 4; kk++)
                wa[kk] = Wfh[kk * M + t];
            #pragma unroll 1
            for (int k = 0; k < M; k += 8) {
                #pragma unroll
                for (int kk = 0; kk < 4; kk++)
                    wb[kk] = Wfh[(k + 4 + kk) * M + t];
                #pragma unroll
                for (int n = 0; n < NT; n++) {
                    const float4 h4 = *reinterpret_cast<const float4*>(s_f + n * M + k);
                    b[n] += h4.x * wa[0] + h4.y * wa[1] + h4.z * wa[2] + h4.w * wa[3];
                }
                if (k + 8 < M) {
                    #pragma unroll
                    for (int kk = 0; kk < 4; kk++)
                        wa[kk] = Wfh[(k + 8 + kk) * M + t];
                }
                #pragma unroll
                for (int n = 0; n < NT; n++) {
                    const float4 h4 = *reinterpret_cast<const float4*>(s_f + n * M + k + 4);
                    b[n] += h4.x * wb[0] + h4.y * wb[1] + h4.z * wb[2] + h4.w * wb[3];
                }
            }
        }

        #pragma unroll
        for (int n = 0; n < NT; n++) {
            if (n < nn) {
                int node = s_node[n];
                if (node & (NNODE - 1)) {        // not a root
                    float f = sigf(b[n]);
                    atomicAdd(&g_hsum[s_parg[n] * M + t], hv[n]);
                    atomicAdd(&g_fcsum[s_parg[n] * M + t], f * cv[n]);
                } else {
                    g_croot[(node >> 16) * M + t] = cv[n];
                }
            }
        }
        __syncthreads();
    }
}

template <bool MATVEC>
__device__ __forceinline__ void do_level_adaptive(
    int s0, int cnt, int G,
    const int* l_tok, const int* l_par, const int* r_tok, const int* r_par,
    const float* Wiouh, const float* Wfh,
    float bio0, float bio1, float bio2, float bfh_t,
    float* s_f, int* s_node, int* s_tok, int* s_parg, int* s_ptok)
{
    if (cnt <= 0) return;
    const long c16 = (long)(((cnt + 15) / 16 + G - 1) / G) * 19;
    const long c8  = (long)(((cnt + 7) / 8 + G - 1) / G) * 11;
    const long c4  = (long)(((cnt + 3) / 4 + G - 1) / G) * 7;
    if (c16 <= c8 && c16 <= c4)
        do_level<16, MATVEC>(s0, cnt, l_tok, l_par, r_tok, r_par, Wiouh, Wfh,
                             bio0, bio1, bio2, bfh_t, s_f, s_node, s_tok, s_parg, s_ptok);
    else if (c8 <= c4)
        do_level<8, MATVEC>(s0, cnt, l_tok, l_par, r_tok, r_par, Wiouh, Wfh,
                            bio0, bio1, bio2, bfh_t, s_f, s_node, s_tok, s_parg, s_ptok);
    else
        do_level<4, MATVEC>(s0, cnt, l_tok, l_par, r_tok, r_par, Wiouh, Wfh,
                            bio0, bio1, bio2, bfh_t, s_f, s_node, s_tok, s_parg, s_ptok);
}

extern "C" __global__ void __launch_bounds__(256, 2)
treelstm_kernel(const int* __restrict__ l_tok, const int* __restrict__ l_par,
                const int* __restrict__ r_tok, const int* __restrict__ r_par,
                const float* __restrict__ emb,
                const float* __restrict__ Wioux, const float* __restrict__ bioux,
                const float* __restrict__ Wiouh, const float* __restrict__ biouh,
                const float* __restrict__ Wfx,   const float* __restrict__ bfx,
                const float* __restrict__ Wfh,   const float* __restrict__ bfh,
                const float* __restrict__ Wh,    const float* __restrict__ bh,
                const float* __restrict__ Wp,    const float* __restrict__ bp,
                float* __restrict__ out)
{
    __shared__ __align__(16) float s_f[16 * M];   // 16 KB, multi-purpose
    __shared__ int s_node[16], s_tok[16], s_parg[16], s_ptok[16];

    const int t   = threadIdx.x;
    const int gid = blockIdx.x * blockDim.x + threadIdx.x;
    const int gs  = gridDim.x * blockDim.x;

    // ---------------- Phase 0: zero state + vocab projections ------------
    {
        float4 z4 = make_float4(0.f, 0.f, 0.f, 0.f);
        float4* h4p = reinterpret_cast<float4*>(g_hsum);
        float4* f4p = reinterpret_cast<float4*>(g_fcsum);
        float4* i4p = reinterpret_cast<float4*>(g_iouacc);
        const int n4 = TOT * M / 4;
        const int n4i = TOT * M3 / 4;
        for (int i = gid; i < n4; i += gs) h4p[i] = z4;
        for (int i = gid; i < n4; i += gs) f4p[i] = z4;
        for (int i = gid; i < n4i; i += gs) i4p[i] = z4;
        for (int i = gid; i < MAXD_CAP; i += gs) { g_hist1[i] = 0; g_hist0[i] = 0; }
        for (int i = gid; i < TOT; i += gs) { g_nchild[i] = 0; g_nichild[i] = 0; }
        if (gid == 0) { g_maxd = 0; g_nleaf = 0; }

        // vocab projections: groups of VNB vocab rows per block
        const int VG = VOCAB / VNB;   // 125
        for (int g = blockIdx.x; g < VG; g += gridDim.x) {
            #pragma unroll
            for (int n = 0; n < VNB; n++)
                s_f[n * M + t] = emb[(g * VNB + n) * M + t];
            __syncthreads();
            float a0[VNB], a1[VNB], a2[VNB], af[VNB];
            #pragma unroll
            for (int n = 0; n < VNB; n++) {
                a0[n] = bioux[t]; a1[n] = bioux[M + t];
                a2[n] = bioux[2 * M + t]; af[n] = bfx[t];
            }
            #pragma unroll 1
            for (int k = 0; k < M; k += 4) {
                #pragma unroll
                for (int kk = 0; kk < 4; kk++) {
                    float w0 = Wioux[(k + kk) * M3 + t];
                    float w1 = Wioux[(k + kk) * M3 + M + t];
                    float w2 = Wioux[(k + kk) * M3 + 2 * M + t];
                    float wf = Wfx[(k + kk) * M + t];
                    #pragma unroll
                    for (int n = 0; n < VNB; n++) {
                        float xv = s_f[n * M + k + kk];
                        a0[n] += xv * w0; a1[n] += xv * w1;
                        a2[n] += xv * w2; af[n] += xv * wf;
                    }
                }
            }
            #pragma unroll
            for (int n = 0; n < VNB; n++) {
                int v = g * VNB + n;
                g_ioux[v * M3 + t]         = a0[n];
                g_ioux[v * M3 + M + t]     = a1[n];
                g_ioux[v * M3 + 2 * M + t] = a2[n];
                g_fxp[v * M + t]           = af[n];
            }
            __syncthreads();
        }
    }
    gsync();

    // loop-invariant biases
    const float bio0 = biouh[t], bio1 = biouh[M + t], bio2 = biouh[2 * M + t];
    const float bfh_t = bfh[t];

    // ---------------- Phase 1: depth walk + child counts ------------------
    for (int i = gid; i < TOT; i += gs) {
        int tree = i >> 16, loc = i & (NNODE - 1);
        const int* parp = tree ? r_par : l_par;
        int d = 0, j = loc;
        while (j) { j = __ldg(parp + j); d++; }
        g_depth[i] = d;
        if (loc) {
            int pg = (tree << 16) + __ldg(parp + loc);
            atomicAdd(&g_nchild[pg], 1);
        }
    }
    gsync();

    // -------- Phase 1b: internal-children counts + leaf h/c tables --------
    for (int i = gid; i < TOT; i += gs) {
        int loc = i & (NNODE - 1);
        if (loc && __ldcg(&g_nchild[i]) > 0) {
            int tree = i >> 16;
            const int* parp = tree ? r_par : l_par;
            int pg = (tree << 16) + __ldg(parp + loc);
            atomicAdd(&g_nichild[pg], 1);
        }
    }
    for (int i = gid; i < VOCAB * M; i += gs) {
        int v = i / M, e = i % M;
        float i0 = g_ioux[v * M3 + e]         + biouh[e];
        float i1 = g_ioux[v * M3 + M + e]     + biouh[M + e];
        float i2 = g_ioux[v * M3 + 2 * M + e] + biouh[2 * M + e];
        float c  = sigf(i0) * tanhf(i2);
        g_cleaf[i] = c;
        g_hleaf[i] = sigf(i1) * tanhf(c);
    }
    gsync();

    // ---------------- Phase 1c: split histogram ---------------------------
    for (int i = gid; i < TOT; i += gs) {
        if (__ldcg(&g_nchild[i]) > 0) {
            int d = g_depth[i];
            if (__ldcg(&g_nichild[i]) > 0) atomicAdd(&g_hist1[d], 1);
            else                            atomicAdd(&g_hist0[d], 1);
            atomicMax(&g_maxd, d);
        }
    }
    gsync();

    // ---------------- Phase 2: serial scan of level offsets --------------
    if (blockIdx.x == 0 && threadIdx.x == 0) {
        int s = 0, md = __ldcg(&g_maxd);
        for (int d = 0; d <= md; d++) {
            int h1 = __ldcg(&g_hist1[d]), h0 = __ldcg(&g_hist0[d]);
            g_startv[d] = s;
            g_cur1[d] = s;
            g_cur0[d] = s + h1;
            s += h1 + h0;
        }
    }
    gsync();

    // ---- Phase 3: scatter nodes; hW_leaf = h_leaf@Wiouh, hfW = h@Wfh+bfh --
    for (int i = gid; i < TOT; i += gs) {
        if (__ldcg(&g_nchild[i]) > 0) {
            int d = g_depth[i];
            int pos = (__ldcg(&g_nichild[i]) > 0) ? atomicAdd(&g_cur1[d], 1)
                                                  : atomicAdd(&g_cur0[d], 1);
            g_order[pos] = i;
        } else {
            int pos = atomicAdd(&g_nleaf, 1);
            g_leaf[pos] = i;
        }
    }
    {
        const int VG = VOCAB / VNB;   // 125
        for (int g = blockIdx.x; g < VG; g += gridDim.x) {
            #pragma unroll
            for (int n = 0; n < VNB; n++)
                s_f[n * M + t] = g_hleaf[(g * VNB + n) * M + t];
            __syncthreads();
            float a0[VNB], a1[VNB], a2[VNB], bf[VNB];
            #pragma unroll
            for (int n = 0; n < VNB; n++) {
                a0[n] = 0.f; a1[n] = 0.f; a2[n] = 0.f; bf[n] = bfh_t;
            }
            #pragma unroll 1
            for (int k = 0; k < M; k += 4) {
                #pragma unroll
                for (int kk = 0; kk < 4; kk++) {
                    float w0 = Wiouh[(k + kk) * M3 + t];
                    float w1 = Wiouh[(k + kk) * M3 + M + t];
                    float w2 = Wiouh[(k + kk) * M3 + 2 * M + t];
                    float wf = Wfh[(k + kk) * M + t];
                    #pragma unroll
                    for (int n = 0; n < VNB; n++) {
                        float xv = s_f[n * M + k + kk];
                        a0[n] += xv * w0; a1[n] += xv * w1;
                        a2[n] += xv * w2; bf[n] += xv * wf;
                    }
                }
            }
            #pragma unroll
            for (int n = 0; n < VNB; n++) {
                int v = g * VNB + n;
                g_hwl[v * M3 + t]         = a0[n];
                g_hwl[v * M3 + M + t]     = a1[n];
                g_hwl[v * M3 + 2 * M + t] = a2[n];
                g_hfw[v * M + t]          = bf[n];
            }
            __syncthreads();
        }
    }
    gsync();

    // ---------------- Phase 4L: bulk leaf scatter --------------------------
    {
        const int nleaf = __ldcg(&g_nleaf);
        const int ngrp = (nleaf + 7) / 8;
        for (int g = blockIdx.x; g < ngrp; g += gridDim.x) {
            const int base = g * 8;
            const int nn = min(8, nleaf - base);
            if (t < 8) {
                int node = g_leaf[base + ((t < nn) ? t : 0)];
                int tree = node >> 16, loc = node & (NNODE - 1);
                const int* tokp = tree ? r_tok : l_tok;
                const int* parp = tree ? r_par : l_par;
                int pl = parp[loc];
                s_node[t] = node;
                s_tok[t]  = tokp[loc];
                s_parg[t] = (tree << 16) + pl;
                s_ptok[t] = tokp[pl];
            }
            __syncthreads();
            #pragma unroll
            for (int n = 0; n < 8; n++) {
                if (n < nn) {
                    int v  = s_tok[n];
                    int pg = s_parg[n];
                    int pv = s_ptok[n];
                    float cl = g_cleaf[v * M + t];
                    float f  = sigf(g_hfw[v * M + t] + g_fxp[pv * M + t]);
                    long pb = (long)pg * M3;
                    atomicAdd(&g_fcsum[pg * M + t], f * cl);
                    atomicAdd(&g_iouacc[pb + t],         g_hwl[v * M3 + t]);
                    atomicAdd(&g_iouacc[pb + M + t],     g_hwl[v * M3 + M + t]);
                    atomicAdd(&g_iouacc[pb + 2 * M + t], g_hwl[v * M3 + 2 * M + t]);
                }
            }
            __syncthreads();
        }
    }
    gsync();

    // ---------------- Phase 4: internal level loop (deepest first) --------
    const int maxd = __ldcg(&g_maxd);
    const int G = gridDim.x;
    for (int d = maxd; d >= 0; --d) {
        const int s0 = __ldcg(&g_startv[d]);
        const int h1 = __ldcg(&g_hist1[d]);
        const int h0 = __ldcg(&g_hist0[d]);
        do_level_adaptive<true>(s0, h1, G, l_tok, l_par, r_tok, r_par, Wiouh, Wfh,
                                bio0, bio1, bio2, bfh_t, s_f, s_node, s_tok, s_parg, s_ptok);
        do_level_adaptive<false>(s0 + h1, h0, G, l_tok, l_par, r_tok, r_par, Wiouh, Wfh,
                                 bio0, bio1, bio2, bfh_t, s_f, s_node, s_tok, s_parg, s_ptok);
        gsync();
    }

    // ---------------- Phase 5: similarity head (block 0) ------------------
    if (blockIdx.x == 0) {
        float cl = __ldcg(&g_croot[t]);
        float cr = __ldcg(&g_croot[M + t]);
        s_f[t]     = cl * cr;
        s_f[M + t] = fabsf(cl - cr);
        __syncthreads();
        float acc = bh[t];
        for (int k = 0; k < 2 * M; k++) acc += s_f[k] * Wh[k * M + t];
        float hid = sigf(acc);
        s_f[2 * M + t] = hid * Wp[2 * t];
        s_f[3 * M + t] = hid * Wp[2 * t + 1];
        __syncthreads();
        if (t == 0) {
            float l0 = bp[0], l1 = bp[1];
            for (int k = 0; k < M; k++) { l0 += s_f[2 * M + k]; l1 += s_f[3 * M + k]; }
            float mx = fmaxf(l0, l1);
            float e0 = expf(l0 - mx), e1 = expf(l1 - mx);
            float inv = 1.0f / (e0 + e1);
            out[0] = e0 * inv;
            out[1] = e1 * inv;
        }
    }
}

extern "C" void kernel_launch(void* const* d_in, const int* in_sizes, int n_in,
                              void* d_out, int out_size)
{
    (void)in_sizes; (void)n_in; (void)out_size;
    int dev = 0;
    cudaGetDevice(&dev);
    int nsm = 0;
    cudaDeviceGetAttribute(&nsm, cudaDevAttrMultiProcessorCount, dev);
    if (nsm <= 0) nsm = 148;

    treelstm_kernel<<<2 * nsm, 256>>>(
        (const int*)d_in[0], (const int*)d_in[1],
        (const int*)d_in[2], (const int*)d_in[3],
        (const float*)d_in[4],
        (const float*)d_in[5], (const float*)d_in[6],
        (const float*)d_in[7], (const float*)d_in[8],
        (const float*)d_in[9], (const float*)d_in[10],
        (const float*)d_in[11], (const float*)d_in[12],
        (const float*)d_in[13], (const float*)d_in[14],
        (const float*)d_in[15], (const float*)d_in[16],
        (float*)d_out);
}

// round 10
// speedup vs baseline: 1.0759x; 1.0759x over previous
#include <cuda_runtime.h>
#include <math.h>

// SimilarityTreeLSTM on GB300: level-parallel tree evaluation in one
// persistent kernel with a software grid barrier.
//
// R9 post-mortem: 402MB iouacc (3x L2) moved the working set to DRAM and
// regressed. R10 keeps the pre-leaf Wiouh skip but with an L2-sized
// footprint:
//  * compact plid slots: only pre-leaf nodes (~33K) own a 768-wide
//    accumulator row (~100MB touched, zeroed exactly [0, npl*M3))
//  * leaves fold hwl[tok] ONLY when the parent is pre-leaf; otherwise the
//    R7/R8 h_sum scatter path (matvec parents never read the accumulator)
//  * matvec do_level path is byte-identical to R8's

#define NNODE 65536
#define TOT   (2 * NNODE)
#define M     256
#define M3    (3 * M)
#define VOCAB 1000
#define VNB   8
#define MAXD_CAP 65536

// ---------------- device scratch (static: no allocations allowed) ----------
__device__ float g_hsum[TOT * M];        // internal+leaf children h (matvec nodes)
__device__ float g_fcsum[TOT * M];
__device__ float g_ioupl[TOT * M3];      // compact pre-leaf iou accum (touched: npl*3KB)
__device__ float g_ioux[VOCAB * M3];     // vocab proj: emb@Wioux + bioux
__device__ float g_fxp[VOCAB * M];       // vocab proj: emb@Wfx + bfx
__device__ float g_hleaf[VOCAB * M];     // leaf h by token
__device__ float g_cleaf[VOCAB * M];     // leaf c by token
__device__ float g_hfw[VOCAB * M];       // h_leaf @ Wfh + bfh
__device__ float g_hwl[VOCAB * M3];      // h_leaf @ Wiouh
__device__ int   g_nchild[TOT];
__device__ int   g_nichild[TOT];         // # internal children
__device__ int   g_plid[TOT];            // compact id for pre-leaf nodes
__device__ int   g_depth[TOT];
__device__ int   g_order[TOT];           // internal nodes by level (matvec|lite)
__device__ int   g_leaf[TOT];            // leaf nodes
__device__ int   g_nleaf;
__device__ int   g_npl;
__device__ int   g_hist1[MAXD_CAP];      // internal w/ internal children
__device__ int   g_hist0[MAXD_CAP];      // internal w/o internal children
__device__ int   g_startv[MAXD_CAP];
__device__ int   g_cur1[MAXD_CAP];
__device__ int   g_cur0[MAXD_CAP];
__device__ int   g_maxd;
__device__ float g_croot[2 * M];
__device__ unsigned g_barcnt;
__device__ unsigned g_sense;

__device__ __forceinline__ float sigf(float x) {
    return 1.0f / (1.0f + expf(-x));
}

// Sense-reversal grid barrier. Requires all blocks co-resident.
__device__ __forceinline__ void gsync() {
    __syncthreads();
    if (threadIdx.x == 0) {
        __threadfence();
        unsigned target = *((volatile unsigned*)&g_sense) + 1u;
        unsigned a = atomicAdd(&g_barcnt, 1u);
        if (a == gridDim.x - 1u) {
            g_barcnt = 0u;
            __threadfence();
            atomicExch(&g_sense, target);
        } else {
            while (*((volatile unsigned*)&g_sense) != target) { __nanosleep(64); }
        }
        __threadfence();
    }
    __syncthreads();
}

// Process a sub-range of one internal-node level, NT nodes per block-group.
// MATVEC=true : R8 path (h_sum holds ALL children h; full Wiouh matvec).
// MATVEC=false: pre-leaf nodes; iou pre-accumulated in compact g_ioupl row.
template <int NT, bool MATVEC>
__device__ void do_level(int s0, int cnt,
                         const int* __restrict__ l_tok, const int* __restrict__ l_par,
                         const int* __restrict__ r_tok, const int* __restrict__ r_par,
                         const float* __restrict__ Wiouh, const float* __restrict__ Wfh,
                         float bio0, float bio1, float bio2, float bfh_t,
                         float* s_f, int* s_node, int* s_tok, int* s_parg, int* s_ptok,
                         int* s_plid)
{
    const int t = threadIdx.x;
    const int ngrp = (cnt + NT - 1) / NT;

    for (int g = blockIdx.x; g < ngrp; g += gridDim.x) {
        const int base = s0 + g * NT;
        const int nn   = min(NT, cnt - g * NT);
        if (t < NT) {
            int idx  = base + ((t < nn) ? t : 0);    // clamp (dup node 0 of grp)
            int node = g_order[idx];
            int tree = node >> 16, loc = node & (NNODE - 1);
            const int* tokp = tree ? r_tok : l_tok;
            const int* parp = tree ? r_par : l_par;
            int pl = parp[loc];
            s_node[t] = node;
            s_tok[t]  = tokp[loc];
            s_parg[t] = (tree << 16) + pl;
            s_ptok[t] = tokp[pl];
            if (!MATVEC) s_plid[t] = g_plid[node];
        }
        __syncthreads();

        float a0[NT], a1[NT], a2[NT];

        if (MATVEC) {
            // load children h sums (bypass L1: updated via L2 atomics)
            #pragma unroll
            for (int n = 0; n < NT; n++)
                s_f[n * M + t] = __ldcg(&g_hsum[s_node[n] * M + t]);
            __syncthreads();

            #pragma unroll
            for (int n = 0; n < NT; n++) {
                int tk = s_tok[n];
                a0[n] = g_ioux[tk * M3 + t]         + bio0;
                a1[n] = g_ioux[tk * M3 + M + t]     + bio1;
                a2[n] = g_ioux[tk * M3 + 2 * M + t] + bio2;
            }

            // ---- Wiouh matvec: explicit two-phase weight double-buffer ----
            float wa0[4], wa1[4], wa2[4], wb0[4], wb1[4], wb2[4];
            #pragma unroll
            for (int kk = 0; kk < 4; kk++) {
                wa0[kk] = Wiouh[kk * M3 + t];
                wa1[kk] = Wiouh[kk * M3 + M + t];
                wa2[kk] = Wiouh[kk * M3 + 2 * M + t];
            }
            #pragma unroll 1
            for (int k = 0; k < M; k += 8) {
                #pragma unroll
                for (int kk = 0; kk < 4; kk++) {
                    wb0[kk] = Wiouh[(k + 4 + kk) * M3 + t];
                    wb1[kk] = Wiouh[(k + 4 + kk) * M3 + M + t];
                    wb2[kk] = Wiouh[(k + 4 + kk) * M3 + 2 * M + t];
                }
                #pragma unroll
                for (int n = 0; n < NT; n++) {
                    const float4 h4 = *reinterpret_cast<const float4*>(s_f + n * M + k);
                    a0[n] += h4.x * wa0[0]; a1[n] += h4.x * wa1[0]; a2[n] += h4.x * wa2[0];
                    a0[n] += h4.y * wa0[1]; a1[n] += h4.y * wa1[1]; a2[n] += h4.y * wa2[1];
                    a0[n] += h4.z * wa0[2]; a1[n] += h4.z * wa1[2]; a2[n] += h4.z * wa2[2];
                    a0[n] += h4.w * wa0[3]; a1[n] += h4.w * wa1[3]; a2[n] += h4.w * wa2[3];
                }
                if (k + 8 < M) {
                    #pragma unroll
                    for (int kk = 0; kk < 4; kk++) {
                        wa0[kk] = Wiouh[(k + 8 + kk) * M3 + t];
                        wa1[kk] = Wiouh[(k + 8 + kk) * M3 + M + t];
                        wa2[kk] = Wiouh[(k + 8 + kk) * M3 + 2 * M + t];
                    }
                }
                #pragma unroll
                for (int n = 0; n < NT; n++) {
                    const float4 h4 = *reinterpret_cast<const float4*>(s_f + n * M + k + 4);
                    a0[n] += h4.x * wb0[0]; a1[n] += h4.x * wb1[0]; a2[n] += h4.x * wb2[0];
                    a0[n] += h4.y * wb0[1]; a1[n] += h4.y * wb1[1]; a2[n] += h4.y * wb2[1];
                    a0[n] += h4.z * wb0[2]; a1[n] += h4.z * wb1[2]; a2[n] += h4.z * wb2[2];
                    a0[n] += h4.w * wb0[3]; a1[n] += h4.w * wb1[3]; a2[n] += h4.w * wb2[3];
                }
            }
        } else {
            // lite: iou already accumulated in compact row (bypass L1)
            #pragma unroll
            for (int n = 0; n < NT; n++) {
                int tk = s_tok[n];
                long pb = (long)s_plid[n] * M3;
                a0[n] = g_ioux[tk * M3 + t]         + bio0 + __ldcg(&g_ioupl[pb + t]);
                a1[n] = g_ioux[tk * M3 + M + t]     + bio1 + __ldcg(&g_ioupl[pb + M + t]);
                a2[n] = g_ioux[tk * M3 + 2 * M + t] + bio2 + __ldcg(&g_ioupl[pb + 2 * M + t]);
            }
        }

        float cv[NT], hv[NT];
        #pragma unroll
        for (int n = 0; n < NT; n++) {
            float fc = __ldcg(&g_fcsum[s_node[n] * M + t]);
            float ig = sigf(a0[n]);
            float og = sigf(a1[n]);
            float ug = tanhf(a2[n]);
            cv[n] = ig * ug + fc;
            hv[n] = og * tanhf(cv[n]);
        }
        __syncthreads();                 // s_f reuse boundary
        #pragma unroll
        for (int n = 0; n < NT; n++) s_f[n * M + t] = hv[n];
        __syncthreads();

        float b[NT];
        #pragma unroll
        for (int n = 0; n < NT; n++)
            b[n] = bfh_t + g_fxp[s_ptok[n] * M + t];

        // ---- Wfh matvec: explicit two-phase weight double-buffer ----
        {
            float wa[4], wb[4];
            #pragma unroll
            for (int kk = 0; kk < 4; kk++)
                wa[kk] = Wfh[kk * M + t];
            #pragma unroll 1
            for (int k = 0; k < M; k += 8) {
                #pragma unroll
                for (int kk = 0; kk < 4; kk++)
                    wb[kk] = Wfh[(k + 4 + kk) * M + t];
                #pragma unroll
                for (int n = 0; n < NT; n++) {
                    const float4 h4 = *reinterpret_cast<const float4*>(s_f + n * M + k);
                    b[n] += h4.x * wa[0] + h4.y * wa[1] + h4.z * wa[2] + h4.w * wa[3];
                }
                if (k + 8 < M) {
                    #pragma unroll
                    for (int kk = 0; kk < 4; kk++)
                        wa[kk] = Wfh[(k + 8 + kk) * M + t];
                }
                #pragma unroll
                for (int n = 0; n < NT; n++) {
                    const float4 h4 = *reinterpret_cast<const float4*>(s_f + n * M + k + 4);
                    b[n] += h4.x * wb[0] + h4.y * wb[1] + h4.z * wb[2] + h4.w * wb[3];
                }
            }
        }

        #pragma unroll
        for (int n = 0; n < NT; n++) {
            if (n < nn) {
                int node = s_node[n];
                if (node & (NNODE - 1)) {        // not a root
                    float f = sigf(b[n]);
                    atomicAdd(&g_hsum[s_parg[n] * M + t], hv[n]);
                    atomicAdd(&g_fcsum[s_parg[n] * M + t], f * cv[n]);
                } else {
                    g_croot[(node >> 16) * M + t] = cv[n];
                }
            }
        }
        __syncthreads();
    }
}

template <bool MATVEC>
__device__ __forceinline__ void do_level_adaptive(
    int s0, int cnt, int G,
    const int* l_tok, const int* l_par, const int* r_tok, const int* r_par,
    const float* Wiouh, const float* Wfh,
    float bio0, float bio1, float bio2, float bfh_t,
    float* s_f, int* s_node, int* s_tok, int* s_parg, int* s_ptok, int* s_plid)
{
    if (cnt <= 0) return;
    const long c16 = (long)(((cnt + 15) / 16 + G - 1) / G) * 19;
    const long c8  = (long)(((cnt + 7) / 8 + G - 1) / G) * 11;
    const long c4  = (long)(((cnt + 3) / 4 + G - 1) / G) * 7;
    if (c16 <= c8 && c16 <= c4)
        do_level<16, MATVEC>(s0, cnt, l_tok, l_par, r_tok, r_par, Wiouh, Wfh,
                             bio0, bio1, bio2, bfh_t, s_f, s_node, s_tok, s_parg, s_ptok, s_plid);
    else if (c8 <= c4)
        do_level<8, MATVEC>(s0, cnt, l_tok, l_par, r_tok, r_par, Wiouh, Wfh,
                            bio0, bio1, bio2, bfh_t, s_f, s_node, s_tok, s_parg, s_ptok, s_plid);
    else
        do_level<4, MATVEC>(s0, cnt, l_tok, l_par, r_tok, r_par, Wiouh, Wfh,
                            bio0, bio1, bio2, bfh_t, s_f, s_node, s_tok, s_parg, s_ptok, s_plid);
}

extern "C" __global__ void __launch_bounds__(256, 2)
treelstm_kernel(const int* __restrict__ l_tok, const int* __restrict__ l_par,
                const int* __restrict__ r_tok, const int* __restrict__ r_par,
                const float* __restrict__ emb,
                const float* __restrict__ Wioux, const float* __restrict__ bioux,
                const float* __restrict__ Wiouh, const float* __restrict__ biouh,
                const float* __restrict__ Wfx,   const float* __restrict__ bfx,
                const float* __restrict__ Wfh,   const float* __restrict__ bfh,
                const float* __restrict__ Wh,    const float* __restrict__ bh,
                const float* __restrict__ Wp,    const float* __restrict__ bp,
                float* __restrict__ out)
{
    __shared__ __align__(16) float s_f[16 * M];   // 16 KB, multi-purpose
    __shared__ int s_node[16], s_tok[16], s_parg[16], s_ptok[16], s_plid[16];
    __shared__ int s_pisl[16];

    const int t   = threadIdx.x;
    const int gid = blockIdx.x * blockDim.x + threadIdx.x;
    const int gs  = gridDim.x * blockDim.x;

    // ---------------- Phase 0: zero state + vocab projections ------------
    {
        float4 z4 = make_float4(0.f, 0.f, 0.f, 0.f);
        float4* h4p = reinterpret_cast<float4*>(g_hsum);
        float4* f4p = reinterpret_cast<float4*>(g_fcsum);
        const int n4 = TOT * M / 4;
        for (int i = gid; i < n4; i += gs) h4p[i] = z4;
        for (int i = gid; i < n4; i += gs) f4p[i] = z4;
        for (int i = gid; i < MAXD_CAP; i += gs) { g_hist1[i] = 0; g_hist0[i] = 0; }
        for (int i = gid; i < TOT; i += gs) { g_nchild[i] = 0; g_nichild[i] = 0; }
        if (gid == 0) { g_maxd = 0; g_nleaf = 0; g_npl = 0; }

        // vocab projections: groups of VNB vocab rows per block
        const int VG = VOCAB / VNB;   // 125
        for (int g = blockIdx.x; g < VG; g += gridDim.x) {
            #pragma unroll
            for (int n = 0; n < VNB; n++)
                s_f[n * M + t] = emb[(g * VNB + n) * M + t];
            __syncthreads();
            float a0[VNB], a1[VNB], a2[VNB], af[VNB];
            #pragma unroll
            for (int n = 0; n < VNB; n++) {
                a0[n] = bioux[t]; a1[n] = bioux[M + t];
                a2[n] = bioux[2 * M + t]; af[n] = bfx[t];
            }
            #pragma unroll 1
            for (int k = 0; k < M; k += 4) {
                #pragma unroll
                for (int kk = 0; kk < 4; kk++) {
                    float w0 = Wioux[(k + kk) * M3 + t];
                    float w1 = Wioux[(k + kk) * M3 + M + t];
                    float w2 = Wioux[(k + kk) * M3 + 2 * M + t];
                    float wf = Wfx[(k + kk) * M + t];
                    #pragma unroll
                    for (int n = 0; n < VNB; n++) {
                        float xv = s_f[n * M + k + kk];
                        a0[n] += xv * w0; a1[n] += xv * w1;
                        a2[n] += xv * w2; af[n] += xv * wf;
                    }
                }
            }
            #pragma unroll
            for (int n = 0; n < VNB; n++) {
                int v = g * VNB + n;
                g_ioux[v * M3 + t]         = a0[n];
                g_ioux[v * M3 + M + t]     = a1[n];
                g_ioux[v * M3 + 2 * M + t] = a2[n];
                g_fxp[v * M + t]           = af[n];
            }
            __syncthreads();
        }
    }
    gsync();

    // loop-invariant biases
    const float bio0 = biouh[t], bio1 = biouh[M + t], bio2 = biouh[2 * M + t];
    const float bfh_t = bfh[t];

    // ---------------- Phase 1: depth walk + child counts ------------------
    for (int i = gid; i < TOT; i += gs) {
        int tree = i >> 16, loc = i & (NNODE - 1);
        const int* parp = tree ? r_par : l_par;
        int d = 0, j = loc;
        while (j) { j = __ldg(parp + j); d++; }
        g_depth[i] = d;
        if (loc) {
            int pg = (tree << 16) + __ldg(parp + loc);
            atomicAdd(&g_nchild[pg], 1);
        }
    }
    gsync();

    // -------- Phase 1b: internal-children counts + leaf h/c tables --------
    for (int i = gid; i < TOT; i += gs) {
        int loc = i & (NNODE - 1);
        if (loc && __ldcg(&g_nchild[i]) > 0) {
            int tree = i >> 16;
            const int* parp = tree ? r_par : l_par;
            int pg = (tree << 16) + __ldg(parp + loc);
            atomicAdd(&g_nichild[pg], 1);
        }
    }
    for (int i = gid; i < VOCAB * M; i += gs) {
        int v = i / M, e = i % M;
        float i0 = g_ioux[v * M3 + e]         + biouh[e];
        float i1 = g_ioux[v * M3 + M + e]     + biouh[M + e];
        float i2 = g_ioux[v * M3 + 2 * M + e] + biouh[2 * M + e];
        float c  = sigf(i0) * tanhf(i2);
        g_cleaf[i] = c;
        g_hleaf[i] = sigf(i1) * tanhf(c);
    }
    gsync();

    // ---------------- Phase 1c: split histogram ---------------------------
    for (int i = gid; i < TOT; i += gs) {
        if (__ldcg(&g_nchild[i]) > 0) {
            int d = g_depth[i];
            if (__ldcg(&g_nichild[i]) > 0) atomicAdd(&g_hist1[d], 1);
            else                            atomicAdd(&g_hist0[d], 1);
            atomicMax(&g_maxd, d);
        }
    }
    gsync();

    // ---------------- Phase 2: serial scan of level offsets --------------
    if (blockIdx.x == 0 && threadIdx.x == 0) {
        int s = 0, md = __ldcg(&g_maxd);
        for (int d = 0; d <= md; d++) {
            int h1 = __ldcg(&g_hist1[d]), h0 = __ldcg(&g_hist0[d]);
            g_startv[d] = s;
            g_cur1[d] = s;
            g_cur0[d] = s + h1;
            s += h1 + h0;
        }
    }
    gsync();

    // ---- Phase 3: scatter nodes + plids; hwl/hfw vocab tables -----------
    for (int i = gid; i < TOT; i += gs) {
        if (__ldcg(&g_nchild[i]) > 0) {
            int d = g_depth[i];
            if (__ldcg(&g_nichild[i]) > 0) {
                g_order[atomicAdd(&g_cur1[d], 1)] = i;
            } else {
                g_order[atomicAdd(&g_cur0[d], 1)] = i;
                g_plid[i] = atomicAdd(&g_npl, 1);
            }
        } else {
            g_leaf[atomicAdd(&g_nleaf, 1)] = i;
        }
    }
    {
        const int VG = VOCAB / VNB;   // 125
        for (int g = blockIdx.x; g < VG; g += gridDim.x) {
            #pragma unroll
            for (int n = 0; n < VNB; n++)
                s_f[n * M + t] = g_hleaf[(g * VNB + n) * M + t];
            __syncthreads();
            float a0[VNB], a1[VNB], a2[VNB], bf[VNB];
            #pragma unroll
            for (int n = 0; n < VNB; n++) {
                a0[n] = 0.f; a1[n] = 0.f; a2[n] = 0.f; bf[n] = bfh_t;
            }
            #pragma unroll 1
            for (int k = 0; k < M; k += 4) {
                #pragma unroll
                for (int kk = 0; kk < 4; kk++) {
                    float w0 = Wiouh[(k + kk) * M3 + t];
                    float w1 = Wiouh[(k + kk) * M3 + M + t];
                    float w2 = Wiouh[(k + kk) * M3 + 2 * M + t];
                    float wf = Wfh[(k + kk) * M + t];
                    #pragma unroll
                    for (int n = 0; n < VNB; n++) {
                        float xv = s_f[n * M + k + kk];
                        a0[n] += xv * w0; a1[n] += xv * w1;
                        a2[n] += xv * w2; bf[n] += xv * wf;
                    }
                }
            }
            #pragma unroll
            for (int n = 0; n < VNB; n++) {
                int v = g * VNB + n;
                g_hwl[v * M3 + t]         = a0[n];
                g_hwl[v * M3 + M + t]     = a1[n];
                g_hwl[v * M3 + 2 * M + t] = a2[n];
                g_hfw[v * M + t]          = bf[n];
            }
            __syncthreads();
        }
    }
    gsync();

    // ------- Phase 3b: zero exactly the used pre-leaf accumulator rows ----
    {
        const long nz = (long)__ldcg(&g_npl) * (M3 / 4);
        float4 z4 = make_float4(0.f, 0.f, 0.f, 0.f);
        float4* p = reinterpret_cast<float4*>(g_ioupl);
        for (long i = gid; i < nz; i += gs) p[i] = z4;
    }
    gsync();

    // ---------------- Phase 4L: bulk leaf scatter --------------------------
    {
        const int nleaf = __ldcg(&g_nleaf);
        const int ngrp = (nleaf + 7) / 8;
        for (int g = blockIdx.x; g < ngrp; g += gridDim.x) {
            const int base = g * 8;
            const int nn = min(8, nleaf - base);
            if (t < 8) {
                int node = g_leaf[base + ((t < nn) ? t : 0)];
                int tree = node >> 16, loc = node & (NNODE - 1);
                const int* tokp = tree ? r_tok : l_tok;
                const int* parp = tree ? r_par : l_par;
                int pl = parp[loc];
                int pg = (tree << 16) + pl;
                s_node[t] = node;
                s_tok[t]  = tokp[loc];
                s_parg[t] = pg;
                s_ptok[t] = tokp[pl];
                int pisl = (__ldcg(&g_nichild[pg]) == 0);
                s_pisl[t] = pisl;
                s_plid[t] = pisl ? g_plid[pg] : 0;
            }
            __syncthreads();
            #pragma unroll
            for (int n = 0; n < 8; n++) {
                if (n < nn) {
                    int v  = s_tok[n];
                    int pg = s_parg[n];
                    int pv = s_ptok[n];
                    float cl = g_cleaf[v * M + t];
                    float f  = sigf(g_hfw[v * M + t] + g_fxp[pv * M + t]);
                    atomicAdd(&g_fcsum[pg * M + t], f * cl);
                    if (s_pisl[n]) {
                        long pb = (long)s_plid[n] * M3;
                        atomicAdd(&g_ioupl[pb + t],         g_hwl[v * M3 + t]);
                        atomicAdd(&g_ioupl[pb + M + t],     g_hwl[v * M3 + M + t]);
                        atomicAdd(&g_ioupl[pb + 2 * M + t], g_hwl[v * M3 + 2 * M + t]);
                    } else {
                        atomicAdd(&g_hsum[pg * M + t], g_hleaf[v * M + t]);
                    }
                }
            }
            __syncthreads();
        }
    }
    gsync();

    // ---------------- Phase 4: internal level loop (deepest first) --------
    const int maxd = __ldcg(&g_maxd);
    const int G = gridDim.x;
    for (int d = maxd; d >= 0; --d) {
        const int s0 = __ldcg(&g_startv[d]);
        const int h1 = __ldcg(&g_hist1[d]);
        const int h0 = __ldcg(&g_hist0[d]);
        do_level_adaptive<true>(s0, h1, G, l_tok, l_par, r_tok, r_par, Wiouh, Wfh,
                                bio0, bio1, bio2, bfh_t, s_f, s_node, s_tok, s_parg,
                                s_ptok, s_plid);
        do_level_adaptive<false>(s0 + h1, h0, G, l_tok, l_par, r_tok, r_par, Wiouh, Wfh,
                                 bio0, bio1, bio2, bfh_t, s_f, s_node, s_tok, s_parg,
                                 s_ptok, s_plid);
        gsync();
    }

    // ---------------- Phase 5: similarity head (block 0) ------------------
    if (blockIdx.x == 0) {
        float cl = __ldcg(&g_croot[t]);
        float cr = __ldcg(&g_croot[M + t]);
        s_f[t]     = cl * cr;
        s_f[M + t] = fabsf(cl - cr);
        __syncthreads();
        float acc = bh[t];
        for (int k = 0; k < 2 * M; k++) acc += s_f[k] * Wh[k * M + t];
        float hid = sigf(acc);
        s_f[2 * M + t] = hid * Wp[2 * t];
        s_f[3 * M + t] = hid * Wp[2 * t + 1];
        __syncthreads();
        if (t == 0) {
            float l0 = bp[0], l1 = bp[1];
            for (int k = 0; k < M; k++) { l0 += s_f[2 * M + k]; l1 += s_f[3 * M + k]; }
            float mx = fmaxf(l0, l1);
            float e0 = expf(l0 - mx), e1 = expf(l1 - mx);
            float inv = 1.0f / (e0 + e1);
            out[0] = e0 * inv;
            out[1] = e1 * inv;
        }
    }
}

extern "C" void kernel_launch(void* const* d_in, const int* in_sizes, int n_in,
                              void* d_out, int out_size)
{
    (void)in_sizes; (void)n_in; (void)out_size;
    int dev = 0;
    cudaGetDevice(&dev);
    int nsm = 0;
    cudaDeviceGetAttribute(&nsm, cudaDevAttrMultiProcessorCount, dev);
    if (nsm <= 0) nsm = 148;

    treelstm_kernel<<<2 * nsm, 256>>>(
        (const int*)d_in[0], (const int*)d_in[1],
        (const int*)d_in[2], (const int*)d_in[3],
        (const float*)d_in[4],
        (const float*)d_in[5], (const float*)d_in[6],
        (const float*)d_in[7], (const float*)d_in[8],
        (const float*)d_in[9], (const float*)d_in[10],
        (const float*)d_in[11], (const float*)d_in[12],
        (const float*)d_in[13], (const float*)d_in[14],
        (const float*)d_in[15], (const float*)d_in[16],
        (float*)d_out);
}